// round 17
// baseline (speedup 1.0000x reference)
#include <cuda_runtime.h>
#include <cuda_fp16.h>
#include <math.h>
#include <stdint.h>

#define F 128
#define MAXN 50048
#define MAXE 800064

// Scratch (__device__ globals; no allocation allowed).
// INVARIANT at kernel_launch entry (zero at load, restored every round):
//   g_pack == 0, g_scanstate == 0, g_scandone == 0.
__device__ __align__(16) float g_W[F * F];               // evolved weight
__device__ __align__(16) __half g_xwh[(size_t)MAXN * F]; // x @ W (fp16)
__device__ float g_dinv[MAXN];                           // rsqrt(deg)
__device__ unsigned long long g_pack[MAXN];              // cnt<<40 | deg*2^24 (zero-invariant)
__device__ int   g_off[MAXN];                            // exclusive scan
__device__ int   g_cur[MAXN];                            // cursors (end = off+cnt after place)
__device__ unsigned g_scanstate[256];                    // per-block aggregates (zero-invariant)
__device__ unsigned g_scandone;                          // scan completion counter (zero-invariant)
__device__ __align__(16) int2 g_edge[MAXE];              // dst-sorted (src, coef)

#define GRU_B 64

__device__ __forceinline__ uint32_t f2tf32(float f) {
    uint32_t u;
    asm("cvt.rna.tf32.f32 %0, %1;" : "=r"(u) : "f"(f));
    return u;
}

__device__ __forceinline__ unsigned long long pack_edge(float w) {
    return (1ULL << 40) | (unsigned long long)__float2uint_rn(w * 16777216.f);
}

// ---------------------------------------------------------------------------
// K1: GRU weight evolution (blocks [0,GRU_B)) ∥ edge histogram (rest).
//     No intra-kernel sync at all — scan moved to K2 (kernel boundary orders).
// ---------------------------------------------------------------------------
__global__ void __launch_bounds__(256) k_gru_hist(
        const float* __restrict__ W0,
        const float* __restrict__ Wih,
        const float* __restrict__ Whh,
        const float* __restrict__ bih,
        const float* __restrict__ bhh,
        const int* __restrict__ dst,
        const float* __restrict__ ew, int E) {

    int b = blockIdx.x;
    int tid = threadIdx.x;

    if (b >= GRU_B) {
        // ------------- histogram: 8 edges/thread, vectorized -------------
        int t = (b - GRU_B) * 256 + tid;
        int e0 = t * 8;
        if (e0 + 7 < E) {
            int4 d0 = __ldg(reinterpret_cast<const int4*>(dst + e0));
            int4 d1 = __ldg(reinterpret_cast<const int4*>(dst + e0 + 4));
            float4 w0 = __ldg(reinterpret_cast<const float4*>(ew + e0));
            float4 w1 = __ldg(reinterpret_cast<const float4*>(ew + e0 + 4));
            atomicAdd(&g_pack[d0.x], pack_edge(w0.x));
            atomicAdd(&g_pack[d0.y], pack_edge(w0.y));
            atomicAdd(&g_pack[d0.z], pack_edge(w0.z));
            atomicAdd(&g_pack[d0.w], pack_edge(w0.w));
            atomicAdd(&g_pack[d1.x], pack_edge(w1.x));
            atomicAdd(&g_pack[d1.y], pack_edge(w1.y));
            atomicAdd(&g_pack[d1.z], pack_edge(w1.z));
            atomicAdd(&g_pack[d1.w], pack_edge(w1.w));
        } else {
            for (int e = e0; e < E; e++)
                atomicAdd(&g_pack[__ldg(dst + e)], pack_edge(__ldg(ew + e)));
        }
        return;
    }

    // ---------------------- GRU weight evolution ----------------------
    int t = b * 256 + tid;
    int i = t >> 7;
    int j = t & 127;
    const float4* w0r = reinterpret_cast<const float4*>(W0 + (size_t)i * F);
    const float4* a_r = reinterpret_cast<const float4*>(Wih + (size_t)j * F);
    const float4* a_z = reinterpret_cast<const float4*>(Wih + (size_t)(j + F) * F);
    const float4* a_n = reinterpret_cast<const float4*>(Wih + (size_t)(j + 2 * F) * F);
    const float4* h_r = reinterpret_cast<const float4*>(Whh + (size_t)j * F);
    const float4* h_z = reinterpret_cast<const float4*>(Whh + (size_t)(j + F) * F);
    const float4* h_n = reinterpret_cast<const float4*>(Whh + (size_t)(j + 2 * F) * F);

    float ir = 0.f, iz = 0.f, in_ = 0.f, hr = 0.f, hz = 0.f, hn = 0.f;
#pragma unroll 4
    for (int k = 0; k < 32; k++) {
        float4 w0 = __ldg(w0r + k);
        float4 v;
        v = __ldg(a_r + k); ir += w0.x * v.x + w0.y * v.y + w0.z * v.z + w0.w * v.w;
        v = __ldg(a_z + k); iz += w0.x * v.x + w0.y * v.y + w0.z * v.z + w0.w * v.w;
        v = __ldg(a_n + k); in_ += w0.x * v.x + w0.y * v.y + w0.z * v.z + w0.w * v.w;
        v = __ldg(h_r + k); hr += w0.x * v.x + w0.y * v.y + w0.z * v.z + w0.w * v.w;
        v = __ldg(h_z + k); hz += w0.x * v.x + w0.y * v.y + w0.z * v.z + w0.w * v.w;
        v = __ldg(h_n + k); hn += w0.x * v.x + w0.y * v.y + w0.z * v.z + w0.w * v.w;
    }
    ir += __ldg(bih + j);
    iz += __ldg(bih + j + F);
    in_ += __ldg(bih + j + 2 * F);
    hr += __ldg(bhh + j);
    hz += __ldg(bhh + j + F);
    hn += __ldg(bhh + j + 2 * F);

    float r = 1.f / (1.f + expf(-(ir + hr)));
    float z = 1.f / (1.f + expf(-(iz + hz)));
    float n = tanhf(in_ + r * hn);
    g_W[t] = (1.f - z) * n + z * __ldg(W0 + t);
}

// ---------------------------------------------------------------------------
// K2: scan (blocks [0,scanB)) | GEMM (blocks [scanB, scanB+gemmB)) |
//     placement (rest, spins on g_scandone).
//     Deadlock proof: __launch_bounds__(256,2) caps regs at 128 -> capacity
//     >= 2 blocks/SM * 148 = 296 > scanB=196, and scan blocks hold the lowest
//     ids -> ALL spin-targets are deterministically wave-1 resident.
// ---------------------------------------------------------------------------
__global__ void __launch_bounds__(256, 2) k_scan_gemm_place(
        const int* __restrict__ src, const int* __restrict__ dst,
        const float* __restrict__ ew, int E,
        const float* __restrict__ x, int N,
        int scanB, int gemmB) {

    int b = blockIdx.x;
    int tid = threadIdx.x;

    if (b < scanB) {
        // -------------------- scan + dinv finalize ----------------------
        __shared__ int sh[256];
        int gid = b * 256 + tid;
        int v = 0;
        if (gid < N) {
            unsigned long long p = g_pack[gid];
            g_pack[gid] = 0ULL;                        // restore invariant
            v = (int)(p >> 40);
            float d = (float)(p & ((1ULL << 40) - 1)) * (1.f / 16777216.f);
            g_dinv[gid] = rsqrtf(d + 1.0f);            // +1 = self-loop
        }
        sh[tid] = v;
        __syncthreads();
#pragma unroll
        for (int o = 1; o < 256; o <<= 1) {
            int t = (tid >= o) ? sh[tid - o] : 0;
            __syncthreads();
            sh[tid] += t;
            __syncthreads();
        }
        int excl = sh[tid] - v;
        int total = sh[255];

        if (tid == 0)
            atomicExch(&g_scanstate[b], (1u << 30) | (unsigned)total);

        int prev = 0;
        if (tid < b) {                  // parallel aggregate wait (all wave-1)
            unsigned s;
            do { s = atomicAdd(&g_scanstate[tid], 0u); } while (!(s >> 30));
            prev = (int)(s & 0x3FFFFFFFu);
        }
        __syncthreads();
        sh[tid] = prev;
        __syncthreads();
#pragma unroll
        for (int o = 128; o; o >>= 1) {
            if (tid < o) sh[tid] += sh[tid + o];
            __syncthreads();
        }
        int base = sh[0];

        if (gid < N) {
            int off = base + excl;
            g_off[gid] = off;
            g_cur[gid] = off;
        }
        __syncthreads();
        __threadfence();
        if (tid == 0) atomicAdd(&g_scandone, 1u);
        return;
    }

    if (b < scanB + gemmB) {
        // ------------- GEMM: xwh = x @ g_W (tf32 mma, fp32 accum) --------
        __shared__ float Xs[128 * 36];
        __shared__ float Ws[32 * 136];
        int warp = tid >> 5, lane = tid & 31;
        int row0 = (b - scanB) * 128;
        int gid = lane >> 2;
        int tig = lane & 3;

        float acc[16][4];
#pragma unroll
        for (int nt = 0; nt < 16; nt++)
#pragma unroll
            for (int c = 0; c < 4; c++) acc[nt][c] = 0.f;

        for (int kt = 0; kt < 4; kt++) {
            __syncthreads();
#pragma unroll
            for (int i = 0; i < 4; i++) {
                int e = tid + i * 256;
                int r = e >> 3, kg = e & 7;
                float4 v = make_float4(0.f, 0.f, 0.f, 0.f);
                if (row0 + r < N)
                    v = __ldg(reinterpret_cast<const float4*>(x + (size_t)(row0 + r) * F + kt * 32) + kg);
                v.x = __uint_as_float(f2tf32(v.x));
                v.y = __uint_as_float(f2tf32(v.y));
                v.z = __uint_as_float(f2tf32(v.z));
                v.w = __uint_as_float(f2tf32(v.w));
                reinterpret_cast<float4*>(Xs)[r * 9 + kg] = v;
            }
#pragma unroll
            for (int i = 0; i < 4; i++) {
                int e = tid + i * 256;
                int r = e >> 5, cg = e & 31;
                float4 v = reinterpret_cast<const float4*>(g_W + (size_t)(kt * 32 + r) * F)[cg];
                v.x = __uint_as_float(f2tf32(v.x));
                v.y = __uint_as_float(f2tf32(v.y));
                v.z = __uint_as_float(f2tf32(v.z));
                v.w = __uint_as_float(f2tf32(v.w));
                reinterpret_cast<float4*>(Ws)[r * 34 + cg] = v;
            }
            __syncthreads();

#pragma unroll
            for (int ks = 0; ks < 4; ks++) {
                int k0 = ks * 8;
                int ar = warp * 16 + gid;
                uint32_t a0 = __float_as_uint(Xs[ar * 36 + k0 + tig]);
                uint32_t a1 = __float_as_uint(Xs[(ar + 8) * 36 + k0 + tig]);
                uint32_t a2 = __float_as_uint(Xs[ar * 36 + k0 + tig + 4]);
                uint32_t a3 = __float_as_uint(Xs[(ar + 8) * 36 + k0 + tig + 4]);
#pragma unroll
                for (int nt = 0; nt < 16; nt++) {
                    int col = nt * 8 + gid;
                    uint32_t b0 = __float_as_uint(Ws[(k0 + tig) * 136 + col]);
                    uint32_t b1 = __float_as_uint(Ws[(k0 + tig + 4) * 136 + col]);
                    asm volatile(
                        "mma.sync.aligned.m16n8k8.row.col.f32.tf32.tf32.f32 "
                        "{%0,%1,%2,%3}, {%4,%5,%6,%7}, {%8,%9}, {%0,%1,%2,%3};"
                        : "+f"(acc[nt][0]), "+f"(acc[nt][1]), "+f"(acc[nt][2]), "+f"(acc[nt][3])
                        : "r"(a0), "r"(a1), "r"(a2), "r"(a3), "r"(b0), "r"(b1));
                }
            }
        }

        int r_lo = row0 + warp * 16 + gid;
        int r_hi = r_lo + 8;
#pragma unroll
        for (int nt = 0; nt < 16; nt++) {
            int c = nt * 8 + 2 * tig;
            if (r_lo < N)
                *reinterpret_cast<__half2*>(g_xwh + (size_t)r_lo * F + c) =
                    __float22half2_rn(make_float2(acc[nt][0], acc[nt][1]));
            if (r_hi < N)
                *reinterpret_cast<__half2*>(g_xwh + (size_t)r_hi * F + c) =
                    __float22half2_rn(make_float2(acc[nt][2], acc[nt][3]));
        }
        return;
    }

    // ----------------- placement: spin on scandone, 4 edges/thread -------
    if (tid == 0) {
        while (atomicAdd(&g_scandone, 0u) < (unsigned)scanB) __nanosleep(64);
    }
    __syncthreads();
    __threadfence();

    if (b == scanB + gemmB)
        g_scanstate[tid] = 0;            // restore invariant (scan finished)

    int t = (b - scanB - gemmB) * 256 + tid;
    int e0 = t * 4;
    if (e0 + 3 < E) {
        int4 ss = __ldg(reinterpret_cast<const int4*>(src + e0));
        int4 dd = __ldg(reinterpret_cast<const int4*>(dst + e0));
        float4 ww = __ldg(reinterpret_cast<const float4*>(ew + e0));
        float c0 = g_dinv[ss.x] * ww.x * g_dinv[dd.x];
        float c1 = g_dinv[ss.y] * ww.y * g_dinv[dd.y];
        float c2 = g_dinv[ss.z] * ww.z * g_dinv[dd.z];
        float c3 = g_dinv[ss.w] * ww.w * g_dinv[dd.w];
        int p0 = atomicAdd(&g_cur[dd.x], 1);
        g_edge[p0] = make_int2(ss.x, __float_as_int(c0));
        int p1 = atomicAdd(&g_cur[dd.y], 1);
        g_edge[p1] = make_int2(ss.y, __float_as_int(c1));
        int p2 = atomicAdd(&g_cur[dd.z], 1);
        g_edge[p2] = make_int2(ss.z, __float_as_int(c2));
        int p3 = atomicAdd(&g_cur[dd.w], 1);
        g_edge[p3] = make_int2(ss.w, __float_as_int(c3));
    } else {
        for (int e = e0; e < E; e++) {
            int s = __ldg(src + e);
            int d = __ldg(dst + e);
            float c = g_dinv[s] * __ldg(ew + e) * g_dinv[d];
            int p = atomicAdd(&g_cur[d], 1);
            g_edge[p] = make_int2(s, __float_as_int(c));
        }
    }
}

// ---------------------------------------------------------------------------
// K3: fused aggregation + tanh + linear output. Warp per dst node.
//     All-fp16 gathers, 8-deep MLP. Block 0 restores g_scandone invariant.
// ---------------------------------------------------------------------------
__global__ void k_agg_out(const float* __restrict__ wlin,
                          const float* __restrict__ blin,
                          float* __restrict__ out, int N) {
    if (blockIdx.x == 0 && threadIdx.x == 0) g_scandone = 0u;  // restore invariant

    int node = (blockIdx.x * blockDim.x + threadIdx.x) >> 5;
    int lane = threadIdx.x & 31;
    if (node >= N) return;

    float di = g_dinv[node];
    float sc = di * di;
    uint2 sv = __ldg(reinterpret_cast<const uint2*>(g_xwh + (size_t)node * F) + lane);
    float2 slo = __half22float2(*reinterpret_cast<__half2*>(&sv.x));
    float2 shi = __half22float2(*reinterpret_cast<__half2*>(&sv.y));
    float ax = sc * slo.x, ay = sc * slo.y, az = sc * shi.x, aw = sc * shi.y;

    int e = g_off[node];
    int end = g_cur[node];          // off + cnt after placement

    for (; e + 8 <= end; e += 8) {
        int2 q[8];
        uint2 a[8];
#pragma unroll
        for (int i = 0; i < 8; i++) q[i] = __ldg(g_edge + e + i);
#pragma unroll
        for (int i = 0; i < 8; i++)
            a[i] = __ldg(reinterpret_cast<const uint2*>(g_xwh + (size_t)q[i].x * F) + lane);
#pragma unroll
        for (int i = 0; i < 8; i++) {
            float c = __int_as_float(q[i].y);
            float2 lo = __half22float2(*reinterpret_cast<__half2*>(&a[i].x));
            float2 hi = __half22float2(*reinterpret_cast<__half2*>(&a[i].y));
            ax += c * lo.x; ay += c * lo.y; az += c * hi.x; aw += c * hi.y;
        }
    }
    for (; e + 2 <= end; e += 2) {
        int2 q0 = __ldg(g_edge + e);
        int2 q1 = __ldg(g_edge + e + 1);
        uint2 a0 = __ldg(reinterpret_cast<const uint2*>(g_xwh + (size_t)q0.x * F) + lane);
        uint2 a1 = __ldg(reinterpret_cast<const uint2*>(g_xwh + (size_t)q1.x * F) + lane);
        float c0 = __int_as_float(q0.y), c1 = __int_as_float(q1.y);
        float2 lo0 = __half22float2(*reinterpret_cast<__half2*>(&a0.x));
        float2 hi0 = __half22float2(*reinterpret_cast<__half2*>(&a0.y));
        float2 lo1 = __half22float2(*reinterpret_cast<__half2*>(&a1.x));
        float2 hi1 = __half22float2(*reinterpret_cast<__half2*>(&a1.y));
        ax += c0 * lo0.x + c1 * lo1.x;
        ay += c0 * lo0.y + c1 * lo1.y;
        az += c0 * hi0.x + c1 * hi1.x;
        aw += c0 * hi0.y + c1 * hi1.y;
    }
    if (e < end) {
        int2 q = __ldg(g_edge + e);
        uint2 a = __ldg(reinterpret_cast<const uint2*>(g_xwh + (size_t)q.x * F) + lane);
        float c = __int_as_float(q.y);
        float2 lo = __half22float2(*reinterpret_cast<__half2*>(&a.x));
        float2 hi = __half22float2(*reinterpret_cast<__half2*>(&a.y));
        ax += c * lo.x; ay += c * lo.y; az += c * hi.x; aw += c * hi.y;
    }

    float4 wv = reinterpret_cast<const float4*>(wlin)[lane];
    float sum = tanhf(ax) * wv.x + tanhf(ay) * wv.y +
                tanhf(az) * wv.z + tanhf(aw) * wv.w;
#pragma unroll
    for (int o = 16; o; o >>= 1) sum += __shfl_xor_sync(0xffffffffu, sum, o);
    if (lane == 0) out[node] = sum + __ldg(blin);
}

// ---------------------------------------------------------------------------
extern "C" void kernel_launch(void* const* d_in, const int* in_sizes, int n_in,
                              void* d_out, int out_size) {
    const float* x    = (const float*)d_in[0];
    const int*   ei   = (const int*)d_in[1];
    const float* ew   = (const float*)d_in[2];
    const float* W0   = (const float*)d_in[3];
    const float* Wih  = (const float*)d_in[4];
    const float* Whh  = (const float*)d_in[5];
    const float* bih  = (const float*)d_in[6];
    const float* bhh  = (const float*)d_in[7];
    const float* wlin = (const float*)d_in[8];
    const float* blin = (const float*)d_in[9];
    float* out = (float*)d_out;

    int N = in_sizes[0] / F;
    int E = in_sizes[2];
    const int* src = ei;
    const int* dst = ei + E;
    int scanB = (N + 255) / 256;                    // 196 (< 296 wave-1 capacity)
    int histB = (E + 2047) / 2048;                  // 8 edges/thread -> 391
    int gemmB = (N + 127) / 128;                    // 391
    int placeB = (E + 1023) / 1024;                 // 4 edges/thread -> 782

    k_gru_hist<<<GRU_B + histB, 256>>>(W0, Wih, Whh, bih, bhh, dst, ew, E);
    k_scan_gemm_place<<<scanB + gemmB + placeB, 256>>>(src, dst, ew, E, x, N,
                                                       scanB, gemmB);
    k_agg_out<<<(N + 7) / 8, 256>>>(wlin, blin, out, N);
}